// round 1
// baseline (speedup 1.0000x reference)
#include <cuda_runtime.h>
#include <cstdint>

#define F_IN 512
#define D1   256
#define D2   64
#define CLS  16
#define MAXN 50176

// ---------------- scratch (device globals; no allocation allowed) ----------------
__device__ float g_H[MAXN * D1];    // H1 pre-propagation, later reused for H2b
__device__ float g_T1[MAXN * D1];   // scatter target layer1 -> final h1
__device__ float g_T2b[MAXN * D1];  // scatter target layer3 -> final h2
__device__ float g_H2a[MAXN * D2];  // x@W20
__device__ float g_T2a[MAXN * D2];  // scatter target layer2 -> h2a
__device__ float g_deg1[MAXN];
__device__ float g_deg2[MAXN];

// ---------------- small utility kernels ----------------
__global__ void zero_kernel(float4* __restrict__ p, int n4) {
    int i = blockIdx.x * blockDim.x + threadIdx.x;
    if (i < n4) p[i] = make_float4(0.f, 0.f, 0.f, 0.f);
}

__global__ void deg_init(float* __restrict__ d1, float* __restrict__ d2, int n) {
    int i = blockIdx.x * blockDim.x + threadIdx.x;
    if (i < n) { d1[i] = 1.0f; d2[i] = 1.0f; }
}

__global__ void deg_count(const int* __restrict__ e1, const int* __restrict__ e2,
                          float* __restrict__ d1, float* __restrict__ d2,
                          int E1, int E2) {
    int i = blockIdx.x * blockDim.x + threadIdx.x;
    if (i < E1) atomicAdd(d1 + e1[E1 + i], 1.0f);
    if (i < E2) atomicAdd(d2 + e2[E2 + i], 1.0f);
}

__global__ void deg_finish(float* __restrict__ d1, float* __restrict__ d2, int n) {
    int i = blockIdx.x * blockDim.x + threadIdx.x;
    if (i < n) { d1[i] = rsqrtf(d1[i]); d2[i] = rsqrtf(d2[i]); }
}

// ---------------- SGEMM: C[M,N] = A[M,K] @ B[K,N], fp32 ----------------
// BM=128, BN=64, BK=16, 256 threads, 8x4 per thread.
__global__ void sgemm_kernel(const float* __restrict__ A, const float* __restrict__ B,
                             float* __restrict__ C, int M, int N, int K)
{
    __shared__ __align__(16) float As[16][128];
    __shared__ __align__(16) float Bs[16][64];

    const int tid = threadIdx.x;
    const int tx = tid & 15;   // 0..15  (col group, 4 cols)
    const int ty = tid >> 4;   // 0..15  (row group, 8 rows)

    const int block_row = blockIdx.y * 128;
    const int block_col = blockIdx.x * 64;

    const int a_row = tid >> 2;          // 0..63
    const int a_k4  = (tid & 3) * 4;     // 0,4,8,12
    const int b_k   = tid >> 4;          // 0..15
    const int b_n4  = (tid & 15) * 4;    // 0..60

    float acc[8][4];
    #pragma unroll
    for (int i = 0; i < 8; i++)
        #pragma unroll
        for (int j = 0; j < 4; j++) acc[i][j] = 0.f;

    for (int k0 = 0; k0 < K; k0 += 16) {
        #pragma unroll
        for (int h = 0; h < 2; h++) {
            int r  = a_row + h * 64;
            int gr = block_row + r;
            float4 v = (gr < M) ? *(const float4*)(A + (size_t)gr * K + k0 + a_k4)
                                : make_float4(0.f, 0.f, 0.f, 0.f);
            As[a_k4 + 0][r] = v.x;
            As[a_k4 + 1][r] = v.y;
            As[a_k4 + 2][r] = v.z;
            As[a_k4 + 3][r] = v.w;
        }
        float4 bv = *(const float4*)(B + (size_t)(k0 + b_k) * N + block_col + b_n4);
        *(float4*)&Bs[b_k][b_n4] = bv;
        __syncthreads();

        #pragma unroll
        for (int k = 0; k < 16; k++) {
            float4 a0 = *(const float4*)&As[k][ty * 8];
            float4 a1 = *(const float4*)&As[k][ty * 8 + 4];
            float4 bq = *(const float4*)&Bs[k][tx * 4];
            float a[8] = {a0.x, a0.y, a0.z, a0.w, a1.x, a1.y, a1.z, a1.w};
            float b[4] = {bq.x, bq.y, bq.z, bq.w};
            #pragma unroll
            for (int i = 0; i < 8; i++)
                #pragma unroll
                for (int j = 0; j < 4; j++)
                    acc[i][j] = fmaf(a[i], b[j], acc[i][j]);
        }
        __syncthreads();
    }

    #pragma unroll
    for (int i = 0; i < 8; i++) {
        int row = block_row + ty * 8 + i;
        if (row < M) {
            float4 v = make_float4(acc[i][0], acc[i][1], acc[i][2], acc[i][3]);
            *(float4*)(C + (size_t)row * N + block_col + tx * 4) = v;
        }
    }
}

// ---------------- edge scatter (vectorized no-return atomics) ----------------
__device__ __forceinline__ void red_add4(float* p, float4 v) {
    asm volatile("red.global.add.v4.f32 [%0], {%1,%2,%3,%4};"
                 :: "l"(p), "f"(v.x), "f"(v.y), "f"(v.z), "f"(v.w) : "memory");
}
__device__ __forceinline__ void red_add2(float* p, float x, float y) {
    asm volatile("red.global.add.v2.f32 [%0], {%1,%2};"
                 :: "l"(p), "f"(x), "f"(y) : "memory");
}

// one warp per edge, 256 floats
__global__ void scatter_d256(const float* __restrict__ H, float* __restrict__ T,
                             const int* __restrict__ ei, const float* __restrict__ dinv, int E)
{
    int w = (blockIdx.x * blockDim.x + threadIdx.x) >> 5;
    if (w >= E) return;
    int lane = threadIdx.x & 31;
    int src = ei[w];
    int dst = ei[E + w];
    float nrm = dinv[src] * dinv[dst];
    const float4* hs = (const float4*)(H + (size_t)src * 256);
    float* tp = T + (size_t)dst * 256;
    float4 v0 = hs[lane];
    float4 v1 = hs[lane + 32];
    v0.x *= nrm; v0.y *= nrm; v0.z *= nrm; v0.w *= nrm;
    v1.x *= nrm; v1.y *= nrm; v1.z *= nrm; v1.w *= nrm;
    red_add4(tp + lane * 4, v0);
    red_add4(tp + 128 + lane * 4, v1);
}

// one warp per edge, 64 floats
__global__ void scatter_d64(const float* __restrict__ H, float* __restrict__ T,
                            const int* __restrict__ ei, const float* __restrict__ dinv, int E)
{
    int w = (blockIdx.x * blockDim.x + threadIdx.x) >> 5;
    if (w >= E) return;
    int lane = threadIdx.x & 31;
    int src = ei[w];
    int dst = ei[E + w];
    float nrm = dinv[src] * dinv[dst];
    const float2* hs = (const float2*)(H + (size_t)src * 64);
    float2 v = hs[lane];
    red_add2(T + (size_t)dst * 64 + lane * 2, v.x * nrm, v.y * nrm);
}

// ---------------- epilogue: out = maybe_relu(T + H*dinv^2 + b), in place on T ----------------
__global__ void epilogue_kernel(float* __restrict__ T, const float* __restrict__ H,
                                const float* __restrict__ dinv, const float* __restrict__ b,
                                int n, int D, int do_relu)
{
    int idx = blockIdx.x * blockDim.x + threadIdx.x;
    int d4 = D >> 2;
    int total = n * d4;
    if (idx >= total) return;
    int i = idx / d4;
    int j4 = (idx - i * d4) * 4;
    float di = dinv[i];
    float sl = di * di;
    size_t off = (size_t)i * D + j4;
    float4 t = *(float4*)(T + off);
    float4 h = *(const float4*)(H + off);
    float4 bb = *(const float4*)(b + j4);
    float4 r;
    r.x = fmaf(h.x, sl, t.x) + bb.x;
    r.y = fmaf(h.y, sl, t.y) + bb.y;
    r.z = fmaf(h.z, sl, t.z) + bb.z;
    r.w = fmaf(h.w, sl, t.w) + bb.w;
    if (do_relu) {
        r.x = fmaxf(r.x, 0.f); r.y = fmaxf(r.y, 0.f);
        r.z = fmaxf(r.z, 0.f); r.w = fmaxf(r.w, 0.f);
    }
    *(float4*)(T + off) = r;
}

// ---------------- final: out = (A1 + A2) @ Wfc + bfc ----------------
// 256 threads/block, one warp per row; Wfc padded in smem for conflict-free reads.
__global__ void final_fc(const float* __restrict__ A1, const float* __restrict__ A2,
                         const float* __restrict__ W, const float* __restrict__ b,
                         float* __restrict__ out, int n)
{
    __shared__ float Ws[D1][17];
    __shared__ float bs[CLS];
    for (int i = threadIdx.x; i < D1 * CLS; i += blockDim.x)
        Ws[i >> 4][i & 15] = W[i];
    if (threadIdx.x < CLS) bs[threadIdx.x] = b[threadIdx.x];
    __syncthreads();

    int warp = threadIdx.x >> 5;
    int lane = threadIdx.x & 31;
    int row = blockIdx.x * (blockDim.x >> 5) + warp;
    if (row >= n) return;

    float acc[CLS];
    #pragma unroll
    for (int c = 0; c < CLS; c++) acc[c] = 0.f;

    const float* r1 = A1 + (size_t)row * D1;
    const float* r2 = A2 + (size_t)row * D1;
    #pragma unroll
    for (int t = 0; t < D1 / 32; t++) {
        int j = lane + t * 32;
        float s = r1[j] + r2[j];
        #pragma unroll
        for (int c = 0; c < CLS; c++)
            acc[c] = fmaf(s, Ws[j][c], acc[c]);
    }
    #pragma unroll
    for (int off = 16; off; off >>= 1)
        #pragma unroll
        for (int c = 0; c < CLS; c++)
            acc[c] += __shfl_down_sync(0xffffffffu, acc[c], off);

    if (lane == 0) {
        float* o = out + (size_t)row * CLS;
        #pragma unroll
        for (int c = 0; c < CLS; c++) o[c] = acc[c] + bs[c];
    }
}

// ---------------- launch ----------------
extern "C" void kernel_launch(void* const* d_in, const int* in_sizes, int n_in,
                              void* d_out, int out_size)
{
    const float* x   = (const float*)d_in[0];
    const int*   e1  = (const int*)d_in[1];
    const int*   e2  = (const int*)d_in[2];
    const float* W10 = (const float*)d_in[3];
    const float* b10 = (const float*)d_in[4];
    const float* W20 = (const float*)d_in[5];
    const float* b20 = (const float*)d_in[6];
    const float* W21 = (const float*)d_in[7];
    const float* b21 = (const float*)d_in[8];
    const float* Wfc = (const float*)d_in[9];
    const float* bfc = (const float*)d_in[10];
    float* out = (float*)d_out;

    int n  = in_sizes[0] / F_IN;
    int E1 = in_sizes[1] / 2;
    int E2 = in_sizes[2] / 2;

    float *H, *T1, *T2b, *H2a, *T2a, *dg1, *dg2;
    cudaGetSymbolAddress((void**)&H,   g_H);
    cudaGetSymbolAddress((void**)&T1,  g_T1);
    cudaGetSymbolAddress((void**)&T2b, g_T2b);
    cudaGetSymbolAddress((void**)&H2a, g_H2a);
    cudaGetSymbolAddress((void**)&T2a, g_T2a);
    cudaGetSymbolAddress((void**)&dg1, g_deg1);
    cudaGetSymbolAddress((void**)&dg2, g_deg2);

    const int tb = 256;

    // degrees -> dinv
    deg_init<<<(n + tb - 1) / tb, tb>>>(dg1, dg2, n);
    int Emax = E1 > E2 ? E1 : E2;
    deg_count<<<(Emax + tb - 1) / tb, tb>>>(e1, e2, dg1, dg2, E1, E2);
    deg_finish<<<(n + tb - 1) / tb, tb>>>(dg1, dg2, n);

    // zero scatter targets
    {
        int n4a = n * D1 / 4;
        int n4b = n * D2 / 4;
        zero_kernel<<<(n4a + tb - 1) / tb, tb>>>((float4*)T1,  n4a);
        zero_kernel<<<(n4a + tb - 1) / tb, tb>>>((float4*)T2b, n4a);
        zero_kernel<<<(n4b + tb - 1) / tb, tb>>>((float4*)T2a, n4b);
    }

    dim3 g256(D1 / 64, (n + 127) / 128);
    dim3 g64 (D2 / 64, (n + 127) / 128);

    // layer 1: h1 = relu(prop1(x@W10) + b10)     (edge1, 256-dim)
    sgemm_kernel<<<g256, tb>>>(x, W10, H, n, D1, F_IN);
    scatter_d256<<<((size_t)E1 * 32 + tb - 1) / tb, tb>>>(H, T1, e1, dg1, E1);
    epilogue_kernel<<<(n * D1 / 4 + tb - 1) / tb, tb>>>(T1, H, dg1, b10, n, D1, 1);

    // layer 2: h2a = prop2(x@W20) + b20          (edge2, 64-dim, no relu)
    sgemm_kernel<<<g64, tb>>>(x, W20, H2a, n, D2, F_IN);
    scatter_d64<<<((size_t)E2 * 32 + tb - 1) / tb, tb>>>(H2a, T2a, e2, dg2, E2);
    epilogue_kernel<<<(n * D2 / 4 + tb - 1) / tb, tb>>>(T2a, H2a, dg2, b20, n, D2, 0);

    // layer 3: h2 = relu(prop2(h2a@W21) + b21)   (edge2, 256-dim); reuse H buffer
    sgemm_kernel<<<g256, tb>>>(T2a, W21, H, n, D1, D2);
    scatter_d256<<<((size_t)E2 * 32 + tb - 1) / tb, tb>>>(H, T2b, e2, dg2, E2);
    epilogue_kernel<<<(n * D1 / 4 + tb - 1) / tb, tb>>>(T2b, H, dg2, b21, n, D1, 1);

    // final dense: out = (h1 + h2) @ Wfc + bfc
    final_fc<<<(n + 7) / 8, tb>>>(T1, T2b, Wfc, bfc, out, n);
}